// round 16
// baseline (speedup 1.0000x reference)
#include <cuda_runtime.h>
#include <cuda_fp16.h>
#include <cstdint>

// Problem constants (fixed by setup_inputs)
#define B_   16
#define QN   75
#define C_   640
#define HW   25
#define MS   625
#define NTOT (B_*QN)      // 1200
#define MPAD 1920         // 15*128 padded query rows per batch
#define NPAD 640          // 5*128 padded support rows per batch
#define SSTRIDE 626       // padded row stride of g_S (fp16 rows 4B-aligned)

// ---------------- scratch (device globals: allocation-free, zero-init) -----
__device__ __align__(16) __half g_qT[(size_t)B_*MPAD*C_];
__device__ __align__(16) __half g_sT[(size_t)B_*NPAD*C_];
__device__ __align__(16) float g_qInv[B_*QN*HW];
__device__ __align__(16) float g_sInv[B_*MS];
// e10 = exp(10 * cosine_sim), fp16 (exp fused into GEMM epilogue)
__device__ __align__(16) __half g_S[(size_t)NTOT*HW*SSTRIDE];

// ======================= helpers ===========================================
__device__ __forceinline__ uint32_t smem_u32(const void* p) {
    uint32_t a;
    asm("{ .reg .u64 t; cvta.to.shared.u64 t, %1; cvt.u32.u64 %0, t; }" : "=r"(a) : "l"(p));
    return a;
}
__device__ __forceinline__ void cp16(uint32_t d, const void* s) {
    asm volatile("cp.async.cg.shared.global [%0], [%1], 16;" :: "r"(d), "l"(s));
}
// fp16 m16n8k16 K-permutation within each 32-block:
// chunk c=(k&7)>>1 (8 halves=16B, owned by thread t4=c), pos=((k&31)>>3)*2+(k&1)
__device__ __forceinline__ int hperm(int k) {
    return (k & ~31) + (((k & 7) >> 1) * 8) + (((k & 31) >> 3) * 2) + (k & 1);
}

// =====================================================================
// K1: merged transpose+norm+fp16+hperm, 512 threads, float4 bulk loads.
// blocks [0,400): support; [400,1600): query.
// =====================================================================
__global__ __launch_bounds__(512) void transpose_norm_kernel(
    const float* __restrict__ query, const float* __restrict__ support)
{
    __shared__ __align__(16) float tile[320*25];
    const int t = threadIdx.x, w = t >> 5, lane = t & 31;
    const int mode = (blockIdx.x >= 400) ? 1 : 0;
    const int bi = mode ? (blockIdx.x - 400) : blockIdx.x;
    const float* src = mode ? query : support;
    const int imgs_per_b = mode ? QN : (MS/HW);     // 75 or 25
    const int b = bi / imgs_per_b, im = bi % imgs_per_b;
    const size_t base = (size_t)bi * (C_*HW);

    __half* dst = mode ? g_qT : g_sT;
    float* inv = mode ? g_qInv : g_sInv;
    const size_t padrow0 = (size_t)b * (mode ? MPAD : NPAD) + (size_t)im * HW;
    const size_t invrow0 = (size_t)b * (mode ? (QN*HW) : MS) + (size_t)im * HW;

    float ss[2] = {0.f, 0.f};
    for (int ch = 0; ch < 2; ch++) {
        const int c0 = ch * 320;   // multiple of 32 -> hperm stays chunk-local
        __syncthreads();
        const float4* s4 = (const float4*)(src + base + (size_t)c0*HW);  // 16B-aligned
        for (int idx = t; idx < 2000; idx += 512)
            ((float4*)tile)[idx] = s4[idx];
        __syncthreads();
#pragma unroll
        for (int slot = 0; slot < 2; slot++) {
            int p = w + slot*16;
            if (p < 25) {
                float s = 0.f;
                __half* drow = dst + (padrow0 + p)*C_ + c0;
                for (int c = lane; c < 320; c += 32) {
                    float v = tile[c*25 + p];   // stride 25: conflict-free
                    s += v*v;
                    drow[hperm(c)] = __float2half_rn(v);
                }
                ss[slot] += s;
            }
        }
    }
#pragma unroll
    for (int slot = 0; slot < 2; slot++) {
        int p = w + slot*16;
        if (p < 25) {
            float s = ss[slot];
            for (int o = 16; o; o >>= 1) s += __shfl_down_sync(0xffffffffu, s, o);
            if (lane == 0) {
                float nn = sqrtf(s);
                float d1 = fmaxf(nn, 1e-12f);
                inv[invrow0 + p] = 1.0f / (d1 * (1e-16f + nn/d1));
            }
        }
    }
}

// =====================================================================
// K2: fp16 m16n8k16 mma.sync GEMM, BK=32, 4-stage cp.async ring with
// wait_group 2 (3 groups in flight). XOR(row&3) chunk swizzle.
// Fused exp epilogue writes e10 fp16. smem 64KB -> 2 CTAs/SM.
// =====================================================================
#define STG_HALVES (128*32)
#define GSM_BYTES (4*2*STG_HALVES*2)   // 65536

__global__ __launch_bounds__(256, 2) void gemm_fp16_kernel()
{
    extern __shared__ __half smh[];
    __half* As = smh;                      // [4][128*32]
    __half* Bs = smh + 4*STG_HALVES;       // [4][128*32]

    const int t = threadIdx.x;
    const int lane = t & 31, wid = t >> 5;
    const int warpM = wid >> 2, warpN = wid & 3;   // 2 x 4 warp grid
    const int g = lane >> 2, t4 = lane & 3;
    const int arow0 = blockIdx.y * 128, brow0 = blockIdx.x * 128;
    const int b = blockIdx.z;
    const int lrow = t >> 2, lc4 = t & 3;          // loader: 64 rows x 4 chunks per pass

    const __half* A  = g_qT + ((size_t)b*MPAD + arow0)*C_;
    const __half* Bp = g_sT + ((size_t)b*NPAD + brow0)*C_;

    float acc[4][4][4];
#pragma unroll
    for (int i = 0; i < 4; i++)
#pragma unroll
        for (int j = 0; j < 4; j++)
#pragma unroll
            for (int k = 0; k < 4; k++) acc[i][j][k] = 0.f;

    auto issue = [&](int kc, int buf) {
        __half* Ad = As + buf*STG_HALVES;
        __half* Bd = Bs + buf*STG_HALVES;
        const __half* Ag = A  + kc*32;
        const __half* Bg = Bp + kc*32;
#pragma unroll
        for (int i = 0; i < 2; i++) {
            const int r = i*64 + lrow;
            const int sw = (lc4 ^ (r & 3)) * 8;    // swizzled chunk slot
            cp16(smem_u32(Ad + r*32 + sw), Ag + (size_t)r*C_ + lc4*8);
            cp16(smem_u32(Bd + r*32 + sw), Bg + (size_t)r*C_ + lc4*8);
        }
        asm volatile("cp.async.commit_group;" ::: "memory");
    };

    issue(0, 0);
    issue(1, 1);
    issue(2, 2);

    const int x4 = (t4 ^ (g & 3)) * 8;   // per-thread constant: row&3 == g&3 always

    for (int kc = 0; kc < 20; kc++) {
        if (kc < 18)      asm volatile("cp.async.wait_group 2;" ::: "memory");
        else if (kc < 19) asm volatile("cp.async.wait_group 1;" ::: "memory");
        else              asm volatile("cp.async.wait_group 0;" ::: "memory");
        __syncthreads();
        // buffer (kc+3)%4 == (kc-1)%4: consumed by all warps before this sync
        if (kc + 3 < 20) issue(kc + 3, (kc + 3) & 3);

        const int cbuf = kc & 3;
        const __half* Awp = As + cbuf*STG_HALVES + (warpM*64 + g)*32 + x4;
        const __half* Bwp = Bs + cbuf*STG_HALVES + (warpN*32 + g)*32 + x4;

        uint4 bV[4];
#pragma unroll
        for (int nf = 0; nf < 4; nf++)
            bV[nf] = *(const uint4*)(Bwp + nf*8*32);

#pragma unroll
        for (int mf = 0; mf < 4; mf++) {
            const uint4 av0 = *(const uint4*)(Awp + (mf*16    )*32);
            const uint4 av1 = *(const uint4*)(Awp + (mf*16 + 8)*32);
#pragma unroll
            for (int ks = 0; ks < 2; ks++) {
                const uint32_t a0 = ks ? av0.z : av0.x;
                const uint32_t a1 = ks ? av1.z : av1.x;
                const uint32_t a2 = ks ? av0.w : av0.y;
                const uint32_t a3 = ks ? av1.w : av1.y;
#pragma unroll
                for (int nf = 0; nf < 4; nf++) {
                    const uint32_t b0 = ks ? bV[nf].z : bV[nf].x;
                    const uint32_t b1 = ks ? bV[nf].w : bV[nf].y;
                    asm volatile(
                        "mma.sync.aligned.m16n8k16.row.col.f32.f16.f16.f32 "
                        "{%0,%1,%2,%3}, {%4,%5,%6,%7}, {%8,%9}, {%0,%1,%2,%3};"
                        : "+f"(acc[mf][nf][0]), "+f"(acc[mf][nf][1]),
                          "+f"(acc[mf][nf][2]), "+f"(acc[mf][nf][3])
                        : "r"(a0), "r"(a1), "r"(a2), "r"(a3),
                          "r"(b0), "r"(b1));
                }
            }
        }
    }

    // fused epilogue: e10 = exp(10 * acc*qv*sv), stored fp16
    const float* qInvB = g_qInv + b*1875;
    const float* sInvB = g_sInv + b*625;
    __half* Cout = g_S + (size_t)b*1875*SSTRIDE;
#pragma unroll
    for (int mf = 0; mf < 4; mf++) {
#pragma unroll
        for (int rr = 0; rr < 2; rr++) {
            const int r = arow0 + warpM*64 + mf*16 + g + rr*8;
            if (r >= 1875) continue;
            const float qv = 10.f * qInvB[r];
            __half* orow = Cout + (size_t)r*SSTRIDE;
#pragma unroll
            for (int nf = 0; nf < 4; nf++) {
                const int c = brow0 + warpN*32 + nf*8 + 2*t4;
                if (c + 1 < 625) {
                    const float e0 = __expf(acc[mf][nf][rr*2+0] * qv * sInvB[c]);
                    const float e1 = __expf(acc[mf][nf][rr*2+1] * qv * sInvB[c+1]);
                    *(__half2*)(orow + c) = __floats2half2_rn(e0, e1);
                } else if (c < 625) {
                    orow[c] = __float2half_rn(__expf(acc[mf][nf][rr*2+0] * qv * sInvB[c]));
                }
            }
        }
    }
}

// =====================================================================
// K3: per-n postprocessing v7b — balanced 50-unit G pass with smem
// atomic merge. FIX: accumulators zeroed by a strided loop that all
// 640 threads cover (R15 bug: one-shot zeroing assumed >=714 threads).
// =====================================================================
#define PNT 640
#define PNW 20
#define POST_FLOATS 17100
#define POST_BYTES  (POST_FLOATS*4)

__global__ __launch_bounds__(PNT, 2) void post_kernel(float* __restrict__ out)
{
    extern __shared__ float sm[];
    float* S0   = sm;            // 15625: e10
    float* cinv = sm + 15625;    // 625
    float* rinv = sm + 16250;    // 32 : raw rowsum, then 1/rowsum
    float* rhsS = sm + 16282;    // 32 : raw 0.5-sum, then 1+0.5*s
    float* Graw = sm + 16314;    // 650 (unscaled G, atomically accumulated)
    float* ys   = sm + 16964;    // 32 : rinv[i]*x[i]
    float* clsS = sm + 16996;    // 8
    float* denomS = sm + 17004;  // 1

    const int n = blockIdx.x;
    const int t = threadIdx.x, w = t >> 5, lane = t & 31;

    // zero ALL accumulators: rinv(32)+rhsS(32)+Graw(650) = sm[16250,16964)
    for (int idx = t; idx < 714; idx += PNT) sm[16250 + idx] = 0.f;

    // pass 1 (column-parallel): load fp16 e10, column sums inline -> cinv
    const __half* Sg = g_S + (size_t)n * HW * SSTRIDE;
    if (t < 625) {
        float cs = 0.f;
#pragma unroll
        for (int i = 0; i < 25; i++) {
            const float e = __half2float(Sg[i*SSTRIDE + t]);
            S0[i*625 + t] = e;
            cs += e;
        }
        cinv[t] = 1.f / cs;
    }
    __syncthreads();

    // G pass over 50 units (tile x j-half): acc -> atomicAdd into Graw;
    // rowsums (i0==0 tiles) and rhs partials (p0==0 tiles) likewise.
    for (int unit = w; unit < 50; unit += PNW) {
        const int tile = unit >> 1, jh = unit & 1;
        const int i0 = (tile/5)*5, p0 = (tile%5)*5;
        const int jend = jh ? 625 : 320;
        float acc[25], racc[5], rs[5];
#pragma unroll
        for (int z = 0; z < 25; z++) acc[z] = 0.f;
#pragma unroll
        for (int z = 0; z < 5; z++) { racc[z] = 0.f; rs[z] = 0.f; }
        for (int j = jh*320 + lane; j < jend; j += 32) {
            const float cj = cinv[j];
            float a[5], c2[5];
#pragma unroll
            for (int z = 0; z < 5; z++) {
                a[z]  = S0[(i0+z)*625 + j] * cj;
                float cv = S0[(p0+z)*625 + j];
                c2[z] = cv * cv;
            }
            if (i0 == 0) {
#pragma unroll
                for (int z = 0; z < 5; z++) rs[z] += c2[z];
            }
            if (p0 == 0) {
#pragma unroll
                for (int z = 0; z < 5; z++) racc[z] += a[z];
            }
#pragma unroll
            for (int u = 0; u < 5; u++)
#pragma unroll
                for (int v = 0; v < 5; v++) acc[u*5+v] += a[u]*c2[v];
        }
#pragma unroll
        for (int z = 0; z < 25; z++) {
            float s = acc[z];
            for (int o = 16; o; o >>= 1) s += __shfl_xor_sync(0xffffffffu, s, o);
            if (lane == 0) atomicAdd(&Graw[(i0 + z/5)*26 + (p0 + z%5)], s);
        }
        if (p0 == 0) {
#pragma unroll
            for (int z = 0; z < 5; z++) {
                float s = racc[z];
                for (int o = 16; o; o >>= 1) s += __shfl_xor_sync(0xffffffffu, s, o);
                if (lane == 0) atomicAdd(&rhsS[i0 + z], s);
            }
        }
        if (i0 == 0) {
#pragma unroll
            for (int z = 0; z < 5; z++) {
                float s = rs[z];
                for (int o = 16; o; o >>= 1) s += __shfl_xor_sync(0xffffffffu, s, o);
                if (lane == 0) atomicAdd(&rinv[p0 + z], s);
            }
        }
    }
    __syncthreads();

    // fixups
    if (t < 25) {
        rinv[t] = 1.f / rinv[t];
        rhsS[t] = 1.f + 0.5f * rhsS[t];
    }
    __syncthreads();

    // Neumann solve (I - 0.25 G) x = rhs, G[i][p] = Graw[i][p]*rinv[p]
    if (w == 0) {
        float gr[25];
        const float rh = (lane < 25) ? rhsS[lane] : 0.f;
        const float ri = (lane < 25) ? rinv[lane] : 0.f;
        if (lane < 25) {
#pragma unroll
            for (int p = 0; p < 25; p++) gr[p] = Graw[lane*26 + p];
        }
        float xi = rh;
        ys[lane] = ri * xi;
        for (int it = 0; it < 16; it++) {
            __syncwarp();
            float s = 0.f;
            if (lane < 25) {
#pragma unroll
                for (int p = 0; p < 25; p++) s += gr[p]*ys[p];
            }
            __syncwarp();
            xi = (lane < 25) ? rh + 0.25f*s : 0.f;
            ys[lane] = ri * xi;
        }
        __syncwarp();
        float dv = xi;
        for (int o = 16; o; o >>= 1) dv += __shfl_xor_sync(0xffffffffu, dv, o);
        if (lane == 0) denomS[0] = dv;
    }
    __syncthreads();

    // predicts[w] = sum_{j in class w} sum_i e10[i,j]^2 * ys[i]  / denom
    if (w < 5) {
        float s = 0.f;
        for (int jj = lane; jj < 125; jj += 32) {
            const int j = w*125 + jj;
            float y = 0.f;
#pragma unroll
            for (int i = 0; i < 25; i++) {
                const float v = S0[i*625 + j];
                y += v*v*ys[i];
            }
            s += y;
        }
        for (int o = 16; o; o >>= 1) s += __shfl_xor_sync(0xffffffffu, s, o);
        if (lane == 0) clsS[w] = s;
    }
    __syncthreads();
    if (t < 5) out[n*5 + t] = clsS[t] / denomS[0];
}

// =====================================================================
extern "C" void kernel_launch(void* const* d_in, const int* in_sizes, int n_in,
                              void* d_out, int out_size)
{
    const float* query   = (const float*)d_in[0];
    const float* support = (const float*)d_in[1];
    float* out = (float*)d_out;

    cudaFuncSetAttribute(post_kernel, cudaFuncAttributeMaxDynamicSharedMemorySize, POST_BYTES);
    cudaFuncSetAttribute(gemm_fp16_kernel, cudaFuncAttributeMaxDynamicSharedMemorySize, GSM_BYTES);

    transpose_norm_kernel<<<1600, 512>>>(query, support);
    dim3 gg(5, 15, B_);   // n-tiles x m-tiles x batch
    gemm_fp16_kernel<<<gg, 256, GSM_BYTES>>>();
    post_kernel<<<NTOT, PNT, POST_BYTES>>>(out);
}

// round 17
// speedup vs baseline: 1.1760x; 1.1760x over previous
#include <cuda_runtime.h>
#include <cuda_fp16.h>
#include <cstdint>

// Problem constants (fixed by setup_inputs)
#define B_   16
#define QN   75
#define C_   640
#define HW   25
#define MS   625
#define NTOT (B_*QN)      // 1200
#define MPAD 1920         // 15*128 padded query rows per batch
#define NPAD 640          // 5*128 padded support rows per batch
#define SSTRIDE 626       // padded row stride of g_S (fp16 rows 4B-aligned)

// ---------------- scratch (device globals: allocation-free, zero-init) -----
__device__ __align__(16) __half g_qT[(size_t)B_*MPAD*C_];
__device__ __align__(16) __half g_sT[(size_t)B_*NPAD*C_];
__device__ __align__(16) float g_qInv[B_*QN*HW];
__device__ __align__(16) float g_sInv[B_*MS];
// e10 = exp(10 * cosine_sim), fp16 (exp fused into GEMM epilogue)
__device__ __align__(16) __half g_S[(size_t)NTOT*HW*SSTRIDE];

// ======================= helpers ===========================================
__device__ __forceinline__ uint32_t smem_u32(const void* p) {
    uint32_t a;
    asm("{ .reg .u64 t; cvta.to.shared.u64 t, %1; cvt.u32.u64 %0, t; }" : "=r"(a) : "l"(p));
    return a;
}
__device__ __forceinline__ void cp16(uint32_t d, const void* s) {
    asm volatile("cp.async.cg.shared.global [%0], [%1], 16;" :: "r"(d), "l"(s));
}
// fp16 m16n8k16 K-permutation within each 32-block:
// chunk c=(k&7)>>1 (8 halves=16B, owned by thread t4=c), pos=((k&31)>>3)*2+(k&1)
__device__ __forceinline__ int hperm(int k) {
    return (k & ~31) + (((k & 7) >> 1) * 8) + (((k & 31) >> 3) * 2) + (k & 1);
}

// =====================================================================
// K1: merged transpose+norm+fp16+hperm, 512 threads, float4 bulk loads.
// blocks [0,400): support; [400,1600): query.  (R14 version, measured best)
// =====================================================================
__global__ __launch_bounds__(512) void transpose_norm_kernel(
    const float* __restrict__ query, const float* __restrict__ support)
{
    __shared__ __align__(16) float tile[320*25];
    const int t = threadIdx.x, w = t >> 5, lane = t & 31;
    const int mode = (blockIdx.x >= 400) ? 1 : 0;
    const int bi = mode ? (blockIdx.x - 400) : blockIdx.x;
    const float* src = mode ? query : support;
    const int imgs_per_b = mode ? QN : (MS/HW);     // 75 or 25
    const int b = bi / imgs_per_b, im = bi % imgs_per_b;
    const size_t base = (size_t)bi * (C_*HW);

    __half* dst = mode ? g_qT : g_sT;
    float* inv = mode ? g_qInv : g_sInv;
    const size_t padrow0 = (size_t)b * (mode ? MPAD : NPAD) + (size_t)im * HW;
    const size_t invrow0 = (size_t)b * (mode ? (QN*HW) : MS) + (size_t)im * HW;

    float ss[2] = {0.f, 0.f};
    for (int ch = 0; ch < 2; ch++) {
        const int c0 = ch * 320;   // multiple of 32 -> hperm stays chunk-local
        __syncthreads();
        const float4* s4 = (const float4*)(src + base + (size_t)c0*HW);  // 16B-aligned
        for (int idx = t; idx < 2000; idx += 512)
            ((float4*)tile)[idx] = s4[idx];
        __syncthreads();
#pragma unroll
        for (int slot = 0; slot < 2; slot++) {
            int p = w + slot*16;
            if (p < 25) {
                float s = 0.f;
                __half* drow = dst + (padrow0 + p)*C_ + c0;
                for (int c = lane; c < 320; c += 32) {
                    float v = tile[c*25 + p];   // stride 25: conflict-free
                    s += v*v;
                    drow[hperm(c)] = __float2half_rn(v);
                }
                ss[slot] += s;
            }
        }
    }
#pragma unroll
    for (int slot = 0; slot < 2; slot++) {
        int p = w + slot*16;
        if (p < 25) {
            float s = ss[slot];
            for (int o = 16; o; o >>= 1) s += __shfl_down_sync(0xffffffffu, s, o);
            if (lane == 0) {
                float nn = sqrtf(s);
                float d1 = fmaxf(nn, 1e-12f);
                inv[invrow0 + p] = 1.0f / (d1 * (1e-16f + nn/d1));
            }
        }
    }
}

// =====================================================================
// K2: fp16 m16n8k16 mma.sync GEMM — R13 configuration (best measured):
// BK=32, 3-stage cp.async ring, wait_group 1, XOR(row&3) chunk swizzle,
// fused exp epilogue writing e10 fp16. smem 48KB -> 2 CTAs/SM.
// =====================================================================
#define STG_HALVES (128*32)
#define GSM_BYTES (3*2*STG_HALVES*2)   // 49152

__global__ __launch_bounds__(256, 2) void gemm_fp16_kernel()
{
    extern __shared__ __half smh[];
    __half* As = smh;                      // [3][128*32]
    __half* Bs = smh + 3*STG_HALVES;       // [3][128*32]

    const int t = threadIdx.x;
    const int lane = t & 31, wid = t >> 5;
    const int warpM = wid >> 2, warpN = wid & 3;   // 2 x 4 warp grid
    const int g = lane >> 2, t4 = lane & 3;
    const int arow0 = blockIdx.y * 128, brow0 = blockIdx.x * 128;
    const int b = blockIdx.z;
    const int lrow = t >> 2, lc4 = t & 3;          // loader: 64 rows x 4 chunks per pass

    const __half* A  = g_qT + ((size_t)b*MPAD + arow0)*C_;
    const __half* Bp = g_sT + ((size_t)b*NPAD + brow0)*C_;

    float acc[4][4][4];
#pragma unroll
    for (int i = 0; i < 4; i++)
#pragma unroll
        for (int j = 0; j < 4; j++)
#pragma unroll
            for (int k = 0; k < 4; k++) acc[i][j][k] = 0.f;

    auto issue = [&](int kc, int buf) {
        __half* Ad = As + buf*STG_HALVES;
        __half* Bd = Bs + buf*STG_HALVES;
        const __half* Ag = A  + kc*32;
        const __half* Bg = Bp + kc*32;
#pragma unroll
        for (int i = 0; i < 2; i++) {
            const int r = i*64 + lrow;
            const int sw = (lc4 ^ (r & 3)) * 8;    // swizzled chunk slot
            cp16(smem_u32(Ad + r*32 + sw), Ag + (size_t)r*C_ + lc4*8);
            cp16(smem_u32(Bd + r*32 + sw), Bg + (size_t)r*C_ + lc4*8);
        }
        asm volatile("cp.async.commit_group;" ::: "memory");
    };

    issue(0, 0);
    issue(1, 1);

    const int x4 = (t4 ^ (g & 3)) * 8;   // per-thread constant: row&3 == g&3 always

    for (int kc = 0; kc < 20; kc++) {
        if (kc < 19) asm volatile("cp.async.wait_group 1;" ::: "memory");
        else         asm volatile("cp.async.wait_group 0;" ::: "memory");
        __syncthreads();
        // buffer (kc+2)%3 == (kc-1)%3: consumed by all warps before this sync
        if (kc + 2 < 20) issue(kc + 2, (kc + 2) % 3);

        const int cbuf = kc % 3;
        const __half* Awp = As + cbuf*STG_HALVES + (warpM*64 + g)*32 + x4;
        const __half* Bwp = Bs + cbuf*STG_HALVES + (warpN*32 + g)*32 + x4;

        uint4 bV[4];
#pragma unroll
        for (int nf = 0; nf < 4; nf++)
            bV[nf] = *(const uint4*)(Bwp + nf*8*32);

#pragma unroll
        for (int mf = 0; mf < 4; mf++) {
            const uint4 av0 = *(const uint4*)(Awp + (mf*16    )*32);
            const uint4 av1 = *(const uint4*)(Awp + (mf*16 + 8)*32);
#pragma unroll
            for (int ks = 0; ks < 2; ks++) {
                const uint32_t a0 = ks ? av0.z : av0.x;
                const uint32_t a1 = ks ? av1.z : av1.x;
                const uint32_t a2 = ks ? av0.w : av0.y;
                const uint32_t a3 = ks ? av1.w : av1.y;
#pragma unroll
                for (int nf = 0; nf < 4; nf++) {
                    const uint32_t b0 = ks ? bV[nf].z : bV[nf].x;
                    const uint32_t b1 = ks ? bV[nf].w : bV[nf].y;
                    asm volatile(
                        "mma.sync.aligned.m16n8k16.row.col.f32.f16.f16.f32 "
                        "{%0,%1,%2,%3}, {%4,%5,%6,%7}, {%8,%9}, {%0,%1,%2,%3};"
                        : "+f"(acc[mf][nf][0]), "+f"(acc[mf][nf][1]),
                          "+f"(acc[mf][nf][2]), "+f"(acc[mf][nf][3])
                        : "r"(a0), "r"(a1), "r"(a2), "r"(a3),
                          "r"(b0), "r"(b1));
                }
            }
        }
    }

    // fused epilogue: e10 = exp(10 * acc*qv*sv), stored fp16
    const float* qInvB = g_qInv + b*1875;
    const float* sInvB = g_sInv + b*625;
    __half* Cout = g_S + (size_t)b*1875*SSTRIDE;
#pragma unroll
    for (int mf = 0; mf < 4; mf++) {
#pragma unroll
        for (int rr = 0; rr < 2; rr++) {
            const int r = arow0 + warpM*64 + mf*16 + g + rr*8;
            if (r >= 1875) continue;
            const float qv = 10.f * qInvB[r];
            __half* orow = Cout + (size_t)r*SSTRIDE;
#pragma unroll
            for (int nf = 0; nf < 4; nf++) {
                const int c = brow0 + warpN*32 + nf*8 + 2*t4;
                if (c + 1 < 625) {
                    const float e0 = __expf(acc[mf][nf][rr*2+0] * qv * sInvB[c]);
                    const float e1 = __expf(acc[mf][nf][rr*2+1] * qv * sInvB[c+1]);
                    *(__half2*)(orow + c) = __floats2half2_rn(e0, e1);
                } else if (c < 625) {
                    orow[c] = __float2half_rn(__expf(acc[mf][nf][rr*2+0] * qv * sInvB[c]));
                }
            }
        }
    }
}

// =====================================================================
// K3: per-n postprocessing — R13 v6 (best measured): pass1 colsum;
// fused G/rhs/rowsum pass (20 warps, 25 tiles); Neumann; class sums.
// =====================================================================
#define PNT 640
#define PNW 20
#define POST_FLOATS 17100
#define POST_BYTES  (POST_FLOATS*4)

__global__ __launch_bounds__(PNT, 2) void post_kernel(float* __restrict__ out)
{
    extern __shared__ float sm[];
    float* S0   = sm;            // 15625: e10
    float* cinv = sm + 15625;    // 625
    float* rinv = sm + 16250;    // 32
    float* rhsS = sm + 16282;    // 32
    float* Graw = sm + 16314;    // 650 (unscaled G)
    float* ys   = sm + 16964;    // 32 : rinv[i]*x[i]
    float* clsS = sm + 16996;    // 8
    float* denomS = sm + 17004;  // 1

    const int n = blockIdx.x;
    const int t = threadIdx.x, w = t >> 5, lane = t & 31;

    // pass 1 (column-parallel): load fp16 e10, column sums inline -> cinv
    const __half* Sg = g_S + (size_t)n * HW * SSTRIDE;
    if (t < 625) {
        float cs = 0.f;
#pragma unroll
        for (int i = 0; i < 25; i++) {
            const float e = __half2float(Sg[i*SSTRIDE + t]);
            S0[i*625 + t] = e;
            cs += e;
        }
        cinv[t] = 1.f / cs;
    }
    __syncthreads();

    // G pass (fused rhs + rowsums):
    //   Graw[i][p] = sum_j cinv[j]*e10[i,j]*e10[p,j]^2
    //   rhs[i]     = 1 + 0.5*sum_j cinv[j]*e10[i,j]   (p0==0 tiles)
    //   rowsum[p]  = sum_j e10[p,j]^2 -> rinv          (i0==0 tiles)
    for (int tile = w; tile < 25; tile += PNW) {
        const int i0 = (tile/5)*5, p0 = (tile%5)*5;
        float acc[25], racc[5], rs[5];
#pragma unroll
        for (int z = 0; z < 25; z++) acc[z] = 0.f;
#pragma unroll
        for (int z = 0; z < 5; z++) { racc[z] = 0.f; rs[z] = 0.f; }
        for (int j = lane; j < 625; j += 32) {
            const float cj = cinv[j];
            float a[5], c2[5];
#pragma unroll
            for (int z = 0; z < 5; z++) {
                a[z]  = S0[(i0+z)*625 + j] * cj;
                float cv = S0[(p0+z)*625 + j];
                c2[z] = cv * cv;
            }
            if (i0 == 0) {
#pragma unroll
                for (int z = 0; z < 5; z++) rs[z] += c2[z];
            }
            if (p0 == 0) {
#pragma unroll
                for (int z = 0; z < 5; z++) racc[z] += a[z];
            }
#pragma unroll
            for (int u = 0; u < 5; u++)
#pragma unroll
                for (int v = 0; v < 5; v++) acc[u*5+v] += a[u]*c2[v];
        }
#pragma unroll
        for (int z = 0; z < 25; z++) {
            float s = acc[z];
            for (int o = 16; o; o >>= 1) s += __shfl_xor_sync(0xffffffffu, s, o);
            if (lane == 0) Graw[(i0 + z/5)*26 + (p0 + z%5)] = s;
        }
        if (p0 == 0) {
#pragma unroll
            for (int z = 0; z < 5; z++) {
                float s = racc[z];
                for (int o = 16; o; o >>= 1) s += __shfl_xor_sync(0xffffffffu, s, o);
                if (lane == 0) rhsS[i0 + z] = 1.f + 0.5f*s;
            }
        }
        if (i0 == 0) {
#pragma unroll
            for (int z = 0; z < 5; z++) {
                float s = rs[z];
                for (int o = 16; o; o >>= 1) s += __shfl_xor_sync(0xffffffffu, s, o);
                if (lane == 0) rinv[p0 + z] = 1.f / s;
            }
        }
    }
    __syncthreads();

    // Neumann solve (I - 0.25 G) x = rhs, G[i][p] = Graw[i][p]*rinv[p]
    if (w == 0) {
        float gr[25];
        const float rh = (lane < 25) ? rhsS[lane] : 0.f;
        const float ri = (lane < 25) ? rinv[lane] : 0.f;
        if (lane < 25) {
#pragma unroll
            for (int p = 0; p < 25; p++) gr[p] = Graw[lane*26 + p];
        }
        float xi = rh;
        ys[lane] = ri * xi;
        for (int it = 0; it < 16; it++) {
            __syncwarp();
            float s = 0.f;
            if (lane < 25) {
#pragma unroll
                for (int p = 0; p < 25; p++) s += gr[p]*ys[p];
            }
            __syncwarp();
            xi = (lane < 25) ? rh + 0.25f*s : 0.f;
            ys[lane] = ri * xi;
        }
        __syncwarp();
        float dv = xi;
        for (int o = 16; o; o >>= 1) dv += __shfl_xor_sync(0xffffffffu, dv, o);
        if (lane == 0) denomS[0] = dv;
    }
    __syncthreads();

    // predicts[w] = sum_{j in class w} sum_i e10[i,j]^2 * ys[i]  / denom
    if (w < 5) {
        float s = 0.f;
        for (int jj = lane; jj < 125; jj += 32) {
            const int j = w*125 + jj;
            float y = 0.f;
#pragma unroll
            for (int i = 0; i < 25; i++) {
                const float v = S0[i*625 + j];
                y += v*v*ys[i];
            }
            s += y;
        }
        for (int o = 16; o; o >>= 1) s += __shfl_xor_sync(0xffffffffu, s, o);
        if (lane == 0) clsS[w] = s;
    }
    __syncthreads();
    if (t < 5) out[n*5 + t] = clsS[t] / denomS[0];
}

// =====================================================================
extern "C" void kernel_launch(void* const* d_in, const int* in_sizes, int n_in,
                              void* d_out, int out_size)
{
    const float* query   = (const float*)d_in[0];
    const float* support = (const float*)d_in[1];
    float* out = (float*)d_out;

    cudaFuncSetAttribute(post_kernel, cudaFuncAttributeMaxDynamicSharedMemorySize, POST_BYTES);
    cudaFuncSetAttribute(gemm_fp16_kernel, cudaFuncAttributeMaxDynamicSharedMemorySize, GSM_BYTES);

    transpose_norm_kernel<<<1600, 512>>>(query, support);
    dim3 gg(5, 15, B_);   // n-tiles x m-tiles x batch
    gemm_fp16_kernel<<<gg, 256, GSM_BYTES>>>();
    post_kernel<<<NTOT, PNT, POST_BYTES>>>(out);
}